// round 15
// baseline (speedup 1.0000x reference)
#include <cuda_runtime.h>
#include <cuda_bf16.h>
#include <math.h>
#include <stdint.h>

#define N_NODES 50000
#define E_EDGES 800000
#define D_IN    256
#define D_HID   256
#define D_OUT_  128

// ---------------- device scratch ----------------
__device__ __nv_bfloat16 g_z1h[N_NODES * 256];
__device__ __nv_bfloat16 g_z1l[N_NODES * 256];
__device__ float         g_h  [N_NODES * 256];
__device__ __nv_bfloat16 g_z2h[N_NODES * 256];
__device__ __nv_bfloat16 g_z2l[N_NODES * 256];
// weights transposed to [n][k], hi/lo split
__device__ __nv_bfloat16 g_w1h[D_HID * D_IN], g_w1l[D_HID * D_IN];
__device__ __nv_bfloat16 g_g1h[D_HID * D_IN], g_g1l[D_HID * D_IN];
__device__ __nv_bfloat16 g_w2h[D_OUT_ * D_HID], g_w2l[D_OUT_ * D_HID];
__device__ __nv_bfloat16 g_g2h[D_OUT_ * D_HID], g_g2l[D_OUT_ * D_HID];
// CSR scratch
__device__ int  g_cnt[N_NODES];
__device__ int  g_cur[N_NODES];
__device__ int  g_rowptr[N_NODES + 1];
__device__ int2 g_epack[E_EDGES];

// ---------------- PTX helpers (arch-portable sm_80+) ----------------
__device__ __forceinline__ uint32_t smem_u32(const void* p) {
    uint32_t a;
    asm("{ .reg .u64 t; cvta.to.shared.u64 t, %1; cvt.u32.u64 %0, t; }" : "=r"(a) : "l"(p));
    return a;
}
__device__ __forceinline__ void cp16(uint32_t dst, const void* src, uint32_t sz) {
    asm volatile("cp.async.cg.shared.global [%0], [%1], 16, %2;"
                 :: "r"(dst), "l"(src), "r"(sz) : "memory");
}
#define CP_COMMIT() asm volatile("cp.async.commit_group;" ::: "memory")
#define CP_WAIT0()  asm volatile("cp.async.wait_group 0;" ::: "memory")
#define LDSM4(r, addr) \
    asm volatile("ldmatrix.sync.aligned.m8n8.x4.shared.b16 {%0,%1,%2,%3}, [%4];" \
                 : "=r"((r)[0]), "=r"((r)[1]), "=r"((r)[2]), "=r"((r)[3]) : "r"(addr))
#define MMA16816(d, a, b) \
    asm volatile("mma.sync.aligned.m16n8k16.row.col.f32.bf16.bf16.f32 " \
                 "{%0,%1,%2,%3}, {%4,%5,%6,%7}, {%8,%9}, {%0,%1,%2,%3};" \
                 : "+f"((d)[0]), "+f"((d)[1]), "+f"((d)[2]), "+f"((d)[3]) \
                 : "r"((a)[0]), "r"((a)[1]), "r"((a)[2]), "r"((a)[3]), \
                   "r"((b)[0]), "r"((b)[1]))

// ---------------- CSR build ----------------
__global__ void zero_counters(int* __restrict__ cnt) {
    int i = blockIdx.x * blockDim.x + threadIdx.x;
    if (i < N_NODES) cnt[i] = 0;
}
__global__ void hist_kernel(const int* __restrict__ rows, int* __restrict__ cnt) {
    int t = blockIdx.x * blockDim.x + threadIdx.x;
    int base = t * 4;
    if (base + 4 <= E_EDGES) {
        int4 r4 = *(const int4*)(rows + base);
        atomicAdd(&cnt[r4.x], 1);
        atomicAdd(&cnt[r4.y], 1);
        atomicAdd(&cnt[r4.z], 1);
        atomicAdd(&cnt[r4.w], 1);
    } else {
        for (int e = base; e < E_EDGES; e++) atomicAdd(&cnt[rows[e]], 1);
    }
}
// scan: exclusive scan of cnt -> rowptr, AND initialize cur = rowptr
__global__ void scan_kernel(const int* __restrict__ cnt, int* __restrict__ rowptr,
                            int* __restrict__ cur) {
    __shared__ int ssum[1024];
    const int tid = threadIdx.x;
    const int CH = (N_NODES + 1023) / 1024;
    int base = tid * CH;
    int s = 0;
    for (int i = 0; i < CH; i++) { int idx = base + i; if (idx < N_NODES) s += cnt[idx]; }
    ssum[tid] = s;
    __syncthreads();
    for (int off = 1; off < 1024; off <<= 1) {
        int v = 0;
        if (tid >= off) v = ssum[tid - off];
        __syncthreads();
        ssum[tid] += v;
        __syncthreads();
    }
    int prefix = (tid == 0) ? 0 : ssum[tid - 1];
    for (int i = 0; i < CH; i++) {
        int idx = base + i;
        if (idx < N_NODES) { rowptr[idx] = prefix; cur[idx] = prefix; prefix += cnt[idx]; }
    }
    if (tid == 1023) rowptr[N_NODES] = prefix;
}
// scatter: 1 edge/thread, cur pre-initialized to rowptr
__global__ void scatter_kernel(const int* __restrict__ rows, const int* __restrict__ cols,
                               const float* __restrict__ vals,
                               int* __restrict__ cur, int2* __restrict__ ep) {
    int e = blockIdx.x * blockDim.x + threadIdx.x;
    if (e < E_EDGES) {
        int r = __ldg(&rows[e]);
        int pos = atomicAdd(&cur[r], 1);
        ep[pos] = make_int2(__ldg(&cols[e]), __float_as_int(__ldg(&vals[e])));
    }
}

// ---------------- all-weight transpose + split (one kernel) ----------------
__global__ void split_all_w(const float* __restrict__ W1, const float* __restrict__ G1,
                            const float* __restrict__ W2, const float* __restrict__ G2,
                            __nv_bfloat16* __restrict__ w1h, __nv_bfloat16* __restrict__ w1l,
                            __nv_bfloat16* __restrict__ g1h, __nv_bfloat16* __restrict__ g1l,
                            __nv_bfloat16* __restrict__ w2h, __nv_bfloat16* __restrict__ w2l,
                            __nv_bfloat16* __restrict__ g2h, __nv_bfloat16* __restrict__ g2l) {
    int i = blockIdx.x * blockDim.x + threadIdx.x;
    const int S1 = 256 * 256;
    const int S2 = 256 * 128;
    const float* src;
    __nv_bfloat16 *oh, *ol;
    int idx, M;
    if (i < S1)                { src = W1; oh = w1h; ol = w1l; idx = i;            M = 256; }
    else if (i < 2 * S1)       { src = G1; oh = g1h; ol = g1l; idx = i - S1;       M = 256; }
    else if (i < 2 * S1 + S2)  { src = W2; oh = w2h; ol = w2l; idx = i - 2 * S1;   M = 128; }
    else if (i < 2 * S1 + 2*S2){ src = G2; oh = g2h; ol = g2l; idx = i - 2*S1 - S2; M = 128; }
    else return;
    int n = idx / 256, k = idx % 256;
    float v = src[(size_t)k * M + n];
    __nv_bfloat16 h = __float2bfloat16(v);
    oh[idx] = h;
    ol[idx] = __float2bfloat16(v - __bfloat162float(h));
}

// ---------------- SpMM: Z = A * src (D=256); 64 threads/row x 4 ch, x4 unroll ----
__global__ void __launch_bounds__(256)
spmm_z(const int* __restrict__ rowptr, const int2* __restrict__ ep,
       const float* __restrict__ src,
       __nv_bfloat16* __restrict__ zh, __nv_bfloat16* __restrict__ zl) {
    const int lane = threadIdx.x & 63;
    const int row = blockIdx.x * 4 + (threadIdx.x >> 6);
    if (row >= N_NODES) return;
    const int c = lane * 4;

    int e    = __ldg(&rowptr[row]);
    int eend = __ldg(&rowptr[row + 1]);
    float4 a0 = make_float4(0.f, 0.f, 0.f, 0.f);
    float4 a1 = a0;

    for (; e + 4 <= eend; e += 4) {
        int2 e0 = __ldg(&ep[e]);
        int2 e1 = __ldg(&ep[e + 1]);
        int2 e2 = __ldg(&ep[e + 2]);
        int2 e3 = __ldg(&ep[e + 3]);
        float4 s0 = *(const float4*)&src[(size_t)e0.x * 256 + c];
        float4 s1 = *(const float4*)&src[(size_t)e1.x * 256 + c];
        float4 s2 = *(const float4*)&src[(size_t)e2.x * 256 + c];
        float4 s3 = *(const float4*)&src[(size_t)e3.x * 256 + c];
        float v0 = __int_as_float(e0.y), v1 = __int_as_float(e1.y);
        float v2 = __int_as_float(e2.y), v3 = __int_as_float(e3.y);
        a0.x = fmaf(v0, s0.x, a0.x); a0.y = fmaf(v0, s0.y, a0.y);
        a0.z = fmaf(v0, s0.z, a0.z); a0.w = fmaf(v0, s0.w, a0.w);
        a1.x = fmaf(v1, s1.x, a1.x); a1.y = fmaf(v1, s1.y, a1.y);
        a1.z = fmaf(v1, s1.z, a1.z); a1.w = fmaf(v1, s1.w, a1.w);
        a0.x = fmaf(v2, s2.x, a0.x); a0.y = fmaf(v2, s2.y, a0.y);
        a0.z = fmaf(v2, s2.z, a0.z); a0.w = fmaf(v2, s2.w, a0.w);
        a1.x = fmaf(v3, s3.x, a1.x); a1.y = fmaf(v3, s3.y, a1.y);
        a1.z = fmaf(v3, s3.z, a1.z); a1.w = fmaf(v3, s3.w, a1.w);
    }
    for (; e < eend; e++) {
        int2 ev = __ldg(&ep[e]);
        float v = __int_as_float(ev.y);
        const float4 sv = *(const float4*)&src[(size_t)ev.x * 256 + c];
        a0.x = fmaf(v, sv.x, a0.x); a0.y = fmaf(v, sv.y, a0.y);
        a0.z = fmaf(v, sv.z, a0.z); a0.w = fmaf(v, sv.w, a0.w);
    }
    float o[4] = {a0.x + a1.x, a0.y + a1.y, a0.z + a1.z, a0.w + a1.w};
    __nv_bfloat16 h[4], l[4];
    #pragma unroll
    for (int j = 0; j < 4; j++) {
        h[j] = __float2bfloat16(o[j]);
        l[j] = __float2bfloat16(o[j] - __bfloat162float(h[j]));
    }
    *(uint2*)&zh[(size_t)row * 256 + c] = *(uint2*)h;
    *(uint2*)&zl[(size_t)row * 256 + c] = *(uint2*)l;
}

// ---------------- fused dual GEMM + gating epilogue ----------------
#define STAGE_B 40960

template <bool RELU>
__global__ void __launch_bounds__(256)
gemm_dual(const __nv_bfloat16* __restrict__ Ah, const __nv_bfloat16* __restrict__ Al,
          const __nv_bfloat16* __restrict__ BWh, const __nv_bfloat16* __restrict__ BWl,
          const __nv_bfloat16* __restrict__ BGh, const __nv_bfloat16* __restrict__ BGl,
          float* __restrict__ O, int nrows, int ldc) {
    extern __shared__ __align__(128) char smem[];
    const int tid  = threadIdx.x;
    const int lane = tid & 31;
    const int wid  = tid >> 5;
    const int mwarp = wid >> 1;
    const int nwarp = wid & 1;
    const int rowBase = blockIdx.x * 128;
    const int colBase = blockIdx.y * 64;
    const uint32_t sb = smem_u32(smem);

    const uint32_t AH = 0, AL = 10240, WH = 20480, WL = 25600, GH = 30720, GL = 35840;

    float accW[2][4][4] = {};
    float accG[2][4][4] = {};

    auto load_stage = [&](int s, int k0) {
        uint32_t base = sb + s * STAGE_B;
        int r = tid >> 2;
        int c = tid & 3;
        uint32_t ro = r * 80 + c * 16;
        #pragma unroll
        for (int half = 0; half < 2; half++) {
            int row = r + half * 64;
            uint32_t ro2 = row * 80 + c * 16;
            int gr = rowBase + row;
            uint32_t sz = (gr < nrows) ? 16u : 0u;
            size_t aoff = (size_t)gr * 256 + k0 + c * 8;
            cp16(base + AH + ro2, Ah + aoff, sz);
            cp16(base + AL + ro2, Al + aoff, sz);
        }
        {
            int gn = colBase + r;
            size_t boff = (size_t)gn * 256 + k0 + c * 8;
            cp16(base + WH + ro, BWh + boff, 16);
            cp16(base + WL + ro, BWl + boff, 16);
            cp16(base + GH + ro, BGh + boff, 16);
            cp16(base + GL + ro, BGl + boff, 16);
        }
        CP_COMMIT();
    };

    auto do_mma = [&](float (&acc)[2][4][4], uint32_t (&a)[8], uint32_t (&b)[8]) {
        #pragma unroll
        for (int mt = 0; mt < 2; mt++)
            #pragma unroll
            for (int nt = 0; nt < 4; nt++)
                MMA16816(acc[mt][nt], &a[mt * 4], &b[(nt >> 1) * 4 + (nt & 1) * 2]);
    };

    load_stage(0, 0);

    for (int ch = 0; ch < 8; ch++) {
        CP_WAIT0();
        __syncthreads();
        if (ch < 7) load_stage((ch + 1) & 1, (ch + 1) * 32);

        uint32_t base = sb + (ch & 1) * STAGE_B;
        #pragma unroll
        for (int j = 0; j < 2; j++) {
            uint32_t ah[8], al[8], bb[8];
            uint32_t aoffb = (mwarp * 32 + (lane & 15)) * 80 + (j * 2 + (lane >> 4)) * 16;
            uint32_t boffb = (nwarp * 32 + (lane & 7) + ((lane >> 4) << 3)) * 80 +
                             (j * 2 + ((lane >> 3) & 1)) * 16;

            LDSM4(&ah[0], base + AH + aoffb);
            LDSM4(&ah[4], base + AH + aoffb + 16 * 80);
            LDSM4(&bb[0], base + WH + boffb);
            LDSM4(&bb[4], base + WH + boffb + 16 * 80);
            do_mma(accW, ah, bb);                      // Ah*Wh
            LDSM4(&al[0], base + AL + aoffb);
            LDSM4(&al[4], base + AL + aoffb + 16 * 80);
            do_mma(accW, al, bb);                      // Al*Wh
            LDSM4(&bb[0], base + WL + boffb);
            LDSM4(&bb[4], base + WL + boffb + 16 * 80);
            do_mma(accW, ah, bb);                      // Ah*Wl
            LDSM4(&bb[0], base + GH + boffb);
            LDSM4(&bb[4], base + GH + boffb + 16 * 80);
            do_mma(accG, ah, bb);                      // Ah*Gh
            do_mma(accG, al, bb);                      // Al*Gh
            LDSM4(&bb[0], base + GL + boffb);
            LDSM4(&bb[4], base + GL + boffb + 16 * 80);
            do_mma(accG, ah, bb);                      // Ah*Gl
        }
        __syncthreads();
    }

    #pragma unroll
    for (int mt = 0; mt < 2; mt++) {
        int r0 = rowBase + mwarp * 32 + mt * 16 + (lane >> 2);
        #pragma unroll
        for (int half = 0; half < 2; half++) {
            int r = r0 + half * 8;
            if (r < nrows) {
                float* cp = O + (size_t)r * ldc + colBase + nwarp * 32 + (lane & 3) * 2;
                #pragma unroll
                for (int nt = 0; nt < 4; nt++) {
                    float s0 = accW[mt][nt][half * 2];
                    float s1 = accW[mt][nt][half * 2 + 1];
                    float q0 = accG[mt][nt][half * 2];
                    float q1 = accG[mt][nt][half * 2 + 1];
                    float o0 = s0 / (1.f + expf(-q0));
                    float o1 = s1 / (1.f + expf(-q1));
                    if (RELU) { o0 = fmaxf(o0, 0.f); o1 = fmaxf(o1, 0.f); }
                    *(float2*)(cp + nt * 8) = make_float2(o0, o1);
                }
            }
        }
    }
}

// ---------------- launch ----------------
extern "C" void kernel_launch(void* const* d_in, const int* in_sizes, int n_in,
                              void* d_out, int out_size) {
    const float* x    = (const float*)d_in[0];
    const int*   rows = (const int*)  d_in[1];
    const int*   cols = (const int*)  d_in[2];
    const float* vals = (const float*)d_in[3];
    const float* W1   = (const float*)d_in[4];
    const float* G1   = (const float*)d_in[5];
    const float* W2   = (const float*)d_in[6];
    const float* G2   = (const float*)d_in[7];
    float* out2 = (float*)d_out;

    __nv_bfloat16 *p_z1h, *p_z1l, *p_z2h, *p_z2l;
    __nv_bfloat16 *p_w1h, *p_w1l, *p_g1h, *p_g1l, *p_w2h, *p_w2l, *p_g2h, *p_g2l;
    float* p_h;
    int *p_cnt, *p_cur, *p_rowptr;
    int2* p_ep;
    cudaGetSymbolAddress((void**)&p_z1h, g_z1h);
    cudaGetSymbolAddress((void**)&p_z1l, g_z1l);
    cudaGetSymbolAddress((void**)&p_z2h, g_z2h);
    cudaGetSymbolAddress((void**)&p_z2l, g_z2l);
    cudaGetSymbolAddress((void**)&p_h, g_h);
    cudaGetSymbolAddress((void**)&p_w1h, g_w1h);
    cudaGetSymbolAddress((void**)&p_w1l, g_w1l);
    cudaGetSymbolAddress((void**)&p_g1h, g_g1h);
    cudaGetSymbolAddress((void**)&p_g1l, g_g1l);
    cudaGetSymbolAddress((void**)&p_w2h, g_w2h);
    cudaGetSymbolAddress((void**)&p_w2l, g_w2l);
    cudaGetSymbolAddress((void**)&p_g2h, g_g2h);
    cudaGetSymbolAddress((void**)&p_g2l, g_g2l);
    cudaGetSymbolAddress((void**)&p_cnt, g_cnt);
    cudaGetSymbolAddress((void**)&p_cur, g_cur);
    cudaGetSymbolAddress((void**)&p_rowptr, g_rowptr);
    cudaGetSymbolAddress((void**)&p_ep, g_epack);

    cudaFuncSetAttribute(gemm_dual<true>, cudaFuncAttributeMaxDynamicSharedMemorySize, 2 * STAGE_B);
    cudaFuncSetAttribute(gemm_dual<false>, cudaFuncAttributeMaxDynamicSharedMemorySize, 2 * STAGE_B);

    // --- CSR build (kernel-only, no memset node) ---
    zero_counters<<<(N_NODES + 255) / 256, 256>>>(p_cnt);
    hist_kernel<<<(E_EDGES / 4 + 255) / 256, 256>>>(rows, p_cnt);
    scan_kernel<<<1, 1024>>>(p_cnt, p_rowptr, p_cur);
    scatter_kernel<<<(E_EDGES + 255) / 256, 256>>>(rows, cols, vals, p_cur, p_ep);

    // --- all weight transposes + splits ---
    {
        int tot = 2 * 256 * 256 + 2 * 256 * 128;
        split_all_w<<<(tot + 255) / 256, 256>>>(W1, G1, W2, G2,
                                                p_w1h, p_w1l, p_g1h, p_g1l,
                                                p_w2h, p_w2l, p_g2h, p_g2l);
    }

    const int rt = (N_NODES + 127) / 128;  // 391

    // --- Z1 = A*x, split ---
    spmm_z<<<(N_NODES + 3) / 4, 256>>>(p_rowptr, p_ep, x, p_z1h, p_z1l);

    // --- h = relu(sigmoid(Z1@G1) * (Z1@W1)) ---
    gemm_dual<true><<<dim3(rt, D_HID / 64), 256, 2 * STAGE_B>>>(
        p_z1h, p_z1l, p_w1h, p_w1l, p_g1h, p_g1l, p_h, N_NODES, D_HID);

    // --- Z2 = A*h, split ---
    spmm_z<<<(N_NODES + 3) / 4, 256>>>(p_rowptr, p_ep, p_h, p_z2h, p_z2l);

    // --- logits = sigmoid(Z2@G2) * (Z2@W2) -> d_out ---
    gemm_dual<false><<<dim3(rt, D_OUT_ / 64), 256, 2 * STAGE_B>>>(
        p_z2h, p_z2l, p_w2h, p_w2l, p_g2h, p_g2l, out2, N_NODES, D_OUT_);
}

// round 17
// speedup vs baseline: 1.0604x; 1.0604x over previous
#include <cuda_runtime.h>
#include <cuda_bf16.h>
#include <math.h>
#include <stdint.h>

#define N_NODES 50000
#define E_EDGES 800000
#define D_IN    256
#define D_HID   256
#define D_OUT_  128

// ---------------- device scratch ----------------
__device__ __nv_bfloat16 g_z1h[N_NODES * 256];
__device__ __nv_bfloat16 g_z1l[N_NODES * 256];
__device__ float         g_h  [N_NODES * 256];
__device__ __nv_bfloat16 g_z2h[N_NODES * 256];
__device__ __nv_bfloat16 g_z2l[N_NODES * 256];
// weights transposed to [n][k], hi/lo split
__device__ __nv_bfloat16 g_w1h[D_HID * D_IN], g_w1l[D_HID * D_IN];
__device__ __nv_bfloat16 g_g1h[D_HID * D_IN], g_g1l[D_HID * D_IN];
__device__ __nv_bfloat16 g_w2h[D_OUT_ * D_HID], g_w2l[D_OUT_ * D_HID];
__device__ __nv_bfloat16 g_g2h[D_OUT_ * D_HID], g_g2l[D_OUT_ * D_HID];
// CSR scratch
__device__ int  g_cnt[N_NODES];
__device__ int  g_cur[N_NODES];
__device__ int  g_rowptr[N_NODES + 1];
__device__ int2 g_epack[E_EDGES];

// ---------------- PTX helpers (arch-portable sm_80+) ----------------
__device__ __forceinline__ uint32_t smem_u32(const void* p) {
    uint32_t a;
    asm("{ .reg .u64 t; cvta.to.shared.u64 t, %1; cvt.u32.u64 %0, t; }" : "=r"(a) : "l"(p));
    return a;
}
__device__ __forceinline__ void cp16(uint32_t dst, const void* src, uint32_t sz) {
    asm volatile("cp.async.cg.shared.global [%0], [%1], 16, %2;"
                 :: "r"(dst), "l"(src), "r"(sz) : "memory");
}
#define CP_COMMIT() asm volatile("cp.async.commit_group;" ::: "memory")
#define CP_WAIT0()  asm volatile("cp.async.wait_group 0;" ::: "memory")
#define LDSM4(r, addr) \
    asm volatile("ldmatrix.sync.aligned.m8n8.x4.shared.b16 {%0,%1,%2,%3}, [%4];" \
                 : "=r"((r)[0]), "=r"((r)[1]), "=r"((r)[2]), "=r"((r)[3]) : "r"(addr))
#define MMA16816(d, a, b) \
    asm volatile("mma.sync.aligned.m16n8k16.row.col.f32.bf16.bf16.f32 " \
                 "{%0,%1,%2,%3}, {%4,%5,%6,%7}, {%8,%9}, {%0,%1,%2,%3};" \
                 : "+f"((d)[0]), "+f"((d)[1]), "+f"((d)[2]), "+f"((d)[3]) \
                 : "r"((a)[0]), "r"((a)[1]), "r"((a)[2]), "r"((a)[3]), \
                   "r"((b)[0]), "r"((b)[1]))

// ---------------- CSR build (byte-exact 387.8us champion config) ----------------
__global__ void zero_counters(int* __restrict__ cnt, int* __restrict__ cur) {
    int i = blockIdx.x * blockDim.x + threadIdx.x;
    if (i < N_NODES) { cnt[i] = 0; cur[i] = 0; }
}
__global__ void hist_kernel(const int* __restrict__ rows, int* __restrict__ cnt) {
    int e = blockIdx.x * blockDim.x + threadIdx.x;
    if (e < E_EDGES) atomicAdd(&cnt[rows[e]], 1);
}
__global__ void scan_kernel(const int* __restrict__ cnt, int* __restrict__ rowptr) {
    __shared__ int ssum[1024];
    const int tid = threadIdx.x;
    const int CH = (N_NODES + 1023) / 1024;
    int base = tid * CH;
    int s = 0;
    for (int i = 0; i < CH; i++) { int idx = base + i; if (idx < N_NODES) s += cnt[idx]; }
    ssum[tid] = s;
    __syncthreads();
    for (int off = 1; off < 1024; off <<= 1) {
        int v = 0;
        if (tid >= off) v = ssum[tid - off];
        __syncthreads();
        ssum[tid] += v;
        __syncthreads();
    }
    int prefix = (tid == 0) ? 0 : ssum[tid - 1];
    for (int i = 0; i < CH; i++) {
        int idx = base + i;
        if (idx < N_NODES) { rowptr[idx] = prefix; prefix += cnt[idx]; }
    }
    if (tid == 1023) rowptr[N_NODES] = prefix;
}
// 4 edges per thread: independent atomic chains for MLP
__global__ void scatter_kernel(const int* __restrict__ rows, const int* __restrict__ cols,
                               const float* __restrict__ vals,
                               const int* __restrict__ rowptr, int* __restrict__ cur,
                               int2* __restrict__ ep) {
    int base = (blockIdx.x * blockDim.x + threadIdx.x) * 4;
    #pragma unroll
    for (int j = 0; j < 4; j++) {
        int e = base + j;
        if (e < E_EDGES) {
            int r = __ldg(&rows[e]);
            int pos = rowptr[r] + atomicAdd(&cur[r], 1);
            ep[pos] = make_int2(__ldg(&cols[e]), __float_as_int(__ldg(&vals[e])));
        }
    }
}

// ---------------- all-weight transpose + split (one kernel) ----------------
__global__ void split_all_w(const float* __restrict__ W1, const float* __restrict__ G1,
                            const float* __restrict__ W2, const float* __restrict__ G2,
                            __nv_bfloat16* __restrict__ w1h, __nv_bfloat16* __restrict__ w1l,
                            __nv_bfloat16* __restrict__ g1h, __nv_bfloat16* __restrict__ g1l,
                            __nv_bfloat16* __restrict__ w2h, __nv_bfloat16* __restrict__ w2l,
                            __nv_bfloat16* __restrict__ g2h, __nv_bfloat16* __restrict__ g2l) {
    int i = blockIdx.x * blockDim.x + threadIdx.x;
    const int S1 = 256 * 256;
    const int S2 = 256 * 128;
    const float* src;
    __nv_bfloat16 *oh, *ol;
    int idx, M;
    if (i < S1)                { src = W1; oh = w1h; ol = w1l; idx = i;            M = 256; }
    else if (i < 2 * S1)       { src = G1; oh = g1h; ol = g1l; idx = i - S1;       M = 256; }
    else if (i < 2 * S1 + S2)  { src = W2; oh = w2h; ol = w2l; idx = i - 2 * S1;   M = 128; }
    else if (i < 2 * S1 + 2*S2){ src = G2; oh = g2h; ol = g2l; idx = i - 2*S1 - S2; M = 128; }
    else return;
    int n = idx / 256, k = idx % 256;
    float v = src[(size_t)k * M + n];
    __nv_bfloat16 h = __float2bfloat16(v);
    oh[idx] = h;
    ol[idx] = __float2bfloat16(v - __bfloat162float(h));
}

// ---------------- SpMM: Z = A * src (D=256); 64 threads/row x 4 ch, x4 unroll ----
__global__ void __launch_bounds__(256)
spmm_z(const int* __restrict__ rowptr, const int2* __restrict__ ep,
       const float* __restrict__ src,
       __nv_bfloat16* __restrict__ zh, __nv_bfloat16* __restrict__ zl) {
    const int lane = threadIdx.x & 63;
    const int row = blockIdx.x * 4 + (threadIdx.x >> 6);
    if (row >= N_NODES) return;
    const int c = lane * 4;

    int e    = __ldg(&rowptr[row]);
    int eend = __ldg(&rowptr[row + 1]);
    float4 a0 = make_float4(0.f, 0.f, 0.f, 0.f);
    float4 a1 = a0;

    for (; e + 4 <= eend; e += 4) {
        int2 e0 = __ldg(&ep[e]);
        int2 e1 = __ldg(&ep[e + 1]);
        int2 e2 = __ldg(&ep[e + 2]);
        int2 e3 = __ldg(&ep[e + 3]);
        float4 s0 = *(const float4*)&src[(size_t)e0.x * 256 + c];
        float4 s1 = *(const float4*)&src[(size_t)e1.x * 256 + c];
        float4 s2 = *(const float4*)&src[(size_t)e2.x * 256 + c];
        float4 s3 = *(const float4*)&src[(size_t)e3.x * 256 + c];
        float v0 = __int_as_float(e0.y), v1 = __int_as_float(e1.y);
        float v2 = __int_as_float(e2.y), v3 = __int_as_float(e3.y);
        a0.x = fmaf(v0, s0.x, a0.x); a0.y = fmaf(v0, s0.y, a0.y);
        a0.z = fmaf(v0, s0.z, a0.z); a0.w = fmaf(v0, s0.w, a0.w);
        a1.x = fmaf(v1, s1.x, a1.x); a1.y = fmaf(v1, s1.y, a1.y);
        a1.z = fmaf(v1, s1.z, a1.z); a1.w = fmaf(v1, s1.w, a1.w);
        a0.x = fmaf(v2, s2.x, a0.x); a0.y = fmaf(v2, s2.y, a0.y);
        a0.z = fmaf(v2, s2.z, a0.z); a0.w = fmaf(v2, s2.w, a0.w);
        a1.x = fmaf(v3, s3.x, a1.x); a1.y = fmaf(v3, s3.y, a1.y);
        a1.z = fmaf(v3, s3.z, a1.z); a1.w = fmaf(v3, s3.w, a1.w);
    }
    for (; e < eend; e++) {
        int2 ev = __ldg(&ep[e]);
        float v = __int_as_float(ev.y);
        const float4 sv = *(const float4*)&src[(size_t)ev.x * 256 + c];
        a0.x = fmaf(v, sv.x, a0.x); a0.y = fmaf(v, sv.y, a0.y);
        a0.z = fmaf(v, sv.z, a0.z); a0.w = fmaf(v, sv.w, a0.w);
    }
    float o[4] = {a0.x + a1.x, a0.y + a1.y, a0.z + a1.z, a0.w + a1.w};
    __nv_bfloat16 h[4], l[4];
    #pragma unroll
    for (int j = 0; j < 4; j++) {
        h[j] = __float2bfloat16(o[j]);
        l[j] = __float2bfloat16(o[j] - __bfloat162float(h[j]));
    }
    *(uint2*)&zh[(size_t)row * 256 + c] = *(uint2*)h;
    *(uint2*)&zl[(size_t)row * 256 + c] = *(uint2*)l;
}

// ---------------- fused dual GEMM + gating epilogue ----------------
#define STAGE_B 40960

template <bool RELU>
__global__ void __launch_bounds__(256)
gemm_dual(const __nv_bfloat16* __restrict__ Ah, const __nv_bfloat16* __restrict__ Al,
          const __nv_bfloat16* __restrict__ BWh, const __nv_bfloat16* __restrict__ BWl,
          const __nv_bfloat16* __restrict__ BGh, const __nv_bfloat16* __restrict__ BGl,
          float* __restrict__ O, int nrows, int ldc) {
    extern __shared__ __align__(128) char smem[];
    const int tid  = threadIdx.x;
    const int lane = tid & 31;
    const int wid  = tid >> 5;
    const int mwarp = wid >> 1;
    const int nwarp = wid & 1;
    const int rowBase = blockIdx.x * 128;
    const int colBase = blockIdx.y * 64;
    const uint32_t sb = smem_u32(smem);

    const uint32_t AH = 0, AL = 10240, WH = 20480, WL = 25600, GH = 30720, GL = 35840;

    float accW[2][4][4] = {};
    float accG[2][4][4] = {};

    auto load_stage = [&](int s, int k0) {
        uint32_t base = sb + s * STAGE_B;
        int r = tid >> 2;
        int c = tid & 3;
        uint32_t ro = r * 80 + c * 16;
        #pragma unroll
        for (int half = 0; half < 2; half++) {
            int row = r + half * 64;
            uint32_t ro2 = row * 80 + c * 16;
            int gr = rowBase + row;
            uint32_t sz = (gr < nrows) ? 16u : 0u;
            size_t aoff = (size_t)gr * 256 + k0 + c * 8;
            cp16(base + AH + ro2, Ah + aoff, sz);
            cp16(base + AL + ro2, Al + aoff, sz);
        }
        {
            int gn = colBase + r;
            size_t boff = (size_t)gn * 256 + k0 + c * 8;
            cp16(base + WH + ro, BWh + boff, 16);
            cp16(base + WL + ro, BWl + boff, 16);
            cp16(base + GH + ro, BGh + boff, 16);
            cp16(base + GL + ro, BGl + boff, 16);
        }
        CP_COMMIT();
    };

    auto do_mma = [&](float (&acc)[2][4][4], uint32_t (&a)[8], uint32_t (&b)[8]) {
        #pragma unroll
        for (int mt = 0; mt < 2; mt++)
            #pragma unroll
            for (int nt = 0; nt < 4; nt++)
                MMA16816(acc[mt][nt], &a[mt * 4], &b[(nt >> 1) * 4 + (nt & 1) * 2]);
    };

    load_stage(0, 0);

    for (int ch = 0; ch < 8; ch++) {
        CP_WAIT0();
        __syncthreads();
        if (ch < 7) load_stage((ch + 1) & 1, (ch + 1) * 32);

        uint32_t base = sb + (ch & 1) * STAGE_B;
        #pragma unroll
        for (int j = 0; j < 2; j++) {
            uint32_t ah[8], al[8], bb[8];
            uint32_t aoffb = (mwarp * 32 + (lane & 15)) * 80 + (j * 2 + (lane >> 4)) * 16;
            uint32_t boffb = (nwarp * 32 + (lane & 7) + ((lane >> 4) << 3)) * 80 +
                             (j * 2 + ((lane >> 3) & 1)) * 16;

            LDSM4(&ah[0], base + AH + aoffb);
            LDSM4(&ah[4], base + AH + aoffb + 16 * 80);
            LDSM4(&bb[0], base + WH + boffb);
            LDSM4(&bb[4], base + WH + boffb + 16 * 80);
            do_mma(accW, ah, bb);                      // Ah*Wh
            LDSM4(&al[0], base + AL + aoffb);
            LDSM4(&al[4], base + AL + aoffb + 16 * 80);
            do_mma(accW, al, bb);                      // Al*Wh
            LDSM4(&bb[0], base + WL + boffb);
            LDSM4(&bb[4], base + WL + boffb + 16 * 80);
            do_mma(accW, ah, bb);                      // Ah*Wl
            LDSM4(&bb[0], base + GH + boffb);
            LDSM4(&bb[4], base + GH + boffb + 16 * 80);
            do_mma(accG, ah, bb);                      // Ah*Gh
            do_mma(accG, al, bb);                      // Al*Gh
            LDSM4(&bb[0], base + GL + boffb);
            LDSM4(&bb[4], base + GL + boffb + 16 * 80);
            do_mma(accG, ah, bb);                      // Ah*Gl
        }
        __syncthreads();
    }

    #pragma unroll
    for (int mt = 0; mt < 2; mt++) {
        int r0 = rowBase + mwarp * 32 + mt * 16 + (lane >> 2);
        #pragma unroll
        for (int half = 0; half < 2; half++) {
            int r = r0 + half * 8;
            if (r < nrows) {
                float* cp = O + (size_t)r * ldc + colBase + nwarp * 32 + (lane & 3) * 2;
                #pragma unroll
                for (int nt = 0; nt < 4; nt++) {
                    float s0 = accW[mt][nt][half * 2];
                    float s1 = accW[mt][nt][half * 2 + 1];
                    float q0 = accG[mt][nt][half * 2];
                    float q1 = accG[mt][nt][half * 2 + 1];
                    float o0 = s0 / (1.f + __expf(-q0));
                    float o1 = s1 / (1.f + __expf(-q1));
                    if (RELU) { o0 = fmaxf(o0, 0.f); o1 = fmaxf(o1, 0.f); }
                    *(float2*)(cp + nt * 8) = make_float2(o0, o1);
                }
            }
        }
    }
}

// ---------------- launch ----------------
extern "C" void kernel_launch(void* const* d_in, const int* in_sizes, int n_in,
                              void* d_out, int out_size) {
    const float* x    = (const float*)d_in[0];
    const int*   rows = (const int*)  d_in[1];
    const int*   cols = (const int*)  d_in[2];
    const float* vals = (const float*)d_in[3];
    const float* W1   = (const float*)d_in[4];
    const float* G1   = (const float*)d_in[5];
    const float* W2   = (const float*)d_in[6];
    const float* G2   = (const float*)d_in[7];
    float* out2 = (float*)d_out;

    __nv_bfloat16 *p_z1h, *p_z1l, *p_z2h, *p_z2l;
    __nv_bfloat16 *p_w1h, *p_w1l, *p_g1h, *p_g1l, *p_w2h, *p_w2l, *p_g2h, *p_g2l;
    float* p_h;
    int *p_cnt, *p_cur, *p_rowptr;
    int2* p_ep;
    cudaGetSymbolAddress((void**)&p_z1h, g_z1h);
    cudaGetSymbolAddress((void**)&p_z1l, g_z1l);
    cudaGetSymbolAddress((void**)&p_z2h, g_z2h);
    cudaGetSymbolAddress((void**)&p_z2l, g_z2l);
    cudaGetSymbolAddress((void**)&p_h, g_h);
    cudaGetSymbolAddress((void**)&p_w1h, g_w1h);
    cudaGetSymbolAddress((void**)&p_w1l, g_w1l);
    cudaGetSymbolAddress((void**)&p_g1h, g_g1h);
    cudaGetSymbolAddress((void**)&p_g1l, g_g1l);
    cudaGetSymbolAddress((void**)&p_w2h, g_w2h);
    cudaGetSymbolAddress((void**)&p_w2l, g_w2l);
    cudaGetSymbolAddress((void**)&p_g2h, g_g2h);
    cudaGetSymbolAddress((void**)&p_g2l, g_g2l);
    cudaGetSymbolAddress((void**)&p_cnt, g_cnt);
    cudaGetSymbolAddress((void**)&p_cur, g_cur);
    cudaGetSymbolAddress((void**)&p_rowptr, g_rowptr);
    cudaGetSymbolAddress((void**)&p_ep, g_epack);

    cudaFuncSetAttribute(gemm_dual<true>, cudaFuncAttributeMaxDynamicSharedMemorySize, 2 * STAGE_B);
    cudaFuncSetAttribute(gemm_dual<false>, cudaFuncAttributeMaxDynamicSharedMemorySize, 2 * STAGE_B);

    // --- CSR build (champion config) ---
    zero_counters<<<(N_NODES + 255) / 256, 256>>>(p_cnt, p_cur);
    hist_kernel<<<(E_EDGES + 255) / 256, 256>>>(rows, p_cnt);
    scan_kernel<<<1, 1024>>>(p_cnt, p_rowptr);
    scatter_kernel<<<(E_EDGES / 4 + 255) / 256, 256>>>(rows, cols, vals, p_rowptr, p_cur, p_ep);

    // --- all weight transposes + splits ---
    {
        int tot = 2 * 256 * 256 + 2 * 256 * 128;
        split_all_w<<<(tot + 255) / 256, 256>>>(W1, G1, W2, G2,
                                                p_w1h, p_w1l, p_g1h, p_g1l,
                                                p_w2h, p_w2l, p_g2h, p_g2l);
    }

    const int rt = (N_NODES + 127) / 128;  // 391

    // --- Z1 = A*x, split ---
    spmm_z<<<(N_NODES + 3) / 4, 256>>>(p_rowptr, p_ep, x, p_z1h, p_z1l);

    // --- h = relu(sigmoid(Z1@G1) * (Z1@W1)) ---
    gemm_dual<true><<<dim3(rt, D_HID / 64), 256, 2 * STAGE_B>>>(
        p_z1h, p_z1l, p_w1h, p_w1l, p_g1h, p_g1l, p_h, N_NODES, D_HID);

    // --- Z2 = A*h, split ---
    spmm_z<<<(N_NODES + 3) / 4, 256>>>(p_rowptr, p_ep, p_h, p_z2h, p_z2l);

    // --- logits = sigmoid(Z2@G2) * (Z2@W2) -> d_out ---
    gemm_dual<false><<<dim3(rt, D_OUT_ / 64), 256, 2 * STAGE_B>>>(
        p_z2h, p_z2l, p_w2h, p_w2l, p_g2h, p_g2l, out2, N_NODES, D_OUT_);
}